// round 3
// baseline (speedup 1.0000x reference)
#include <cuda_runtime.h>
#include <math.h>
#include <stdint.h>

// Problem constants
#define S_LEN  2048
#define DMODEL 2048
#define HDIM   128
#define NH     16
#define NG     4
#define BATCH  2
#define KVLD   (NG * HDIM)   // 512

// Attention tiling
#define BQ    128
#define BK    64
#define QP    144   // Q/K smem pitch (mod 32 == 16 -> conflict-free float4 frags)
#define VP    80    // Vt pitch
#define PP    80    // P pitch
#define NTO   16    // HDIM/8 output n-tiles
#define NTS   8     // BK/8 score n-tiles
#define NJT   (S_LEN / BK)   // 32

// Projection tiling
#define PTM   256
#define PTN   128
#define PTK   32
#define GP    48    // proj smem pitch

// Scratch for attention output [B*S, DMODEL] (pre-projection), tf32-rounded fp32.
__device__ float g_attn[(size_t)BATCH * S_LEN * DMODEL];

__device__ __forceinline__ float f2tf(float x) {
    unsigned u;
    asm("cvt.rna.tf32.f32 %0, %1;" : "=r"(u) : "f"(x));
    return __uint_as_float(u);
}

__device__ __forceinline__ float ex2(float x) {
    float r;
    asm("ex2.approx.f32 %0, %1;" : "=f"(r) : "f"(x));
    return r;
}

__device__ __forceinline__ void mma_tf32(float c[4],
    float a0, float a1, float a2, float a3, float b0, float b1)
{
    asm volatile(
        "mma.sync.aligned.m16n8k8.row.col.f32.tf32.tf32.f32 "
        "{%0,%1,%2,%3}, {%4,%5,%6,%7}, {%8,%9}, {%0,%1,%2,%3};"
        : "+f"(c[0]), "+f"(c[1]), "+f"(c[2]), "+f"(c[3])
        : "r"(__float_as_uint(a0)), "r"(__float_as_uint(a1)),
          "r"(__float_as_uint(a2)), "r"(__float_as_uint(a3)),
          "r"(__float_as_uint(b0)), "r"(__float_as_uint(b1)));
}

// ---------------------------------------------------------------------------
// Flash attention, tf32 mma, online softmax (base-2), vectorized fragments.
// Grid: (S/BQ, NH, B). Block: 256 threads = 8 warps; warp owns 16 Q rows.
// k-permutation: within each K=32 chunk, mma step s consumes component s of
// float4s at columns [4*tig] and [16+4*tig]; A and B agree -> correct sum.
// ---------------------------------------------------------------------------
__global__ __launch_bounds__(256, 1)
void attn_kernel(const float* __restrict__ q,
                 const float* __restrict__ k,
                 const float* __restrict__ v)
{
    extern __shared__ float sm[];
    float* Qs = sm;                       // BQ x QP
    float* Ks = Qs + BQ * QP;             // BK x QP
    float* Vt = Ks + BK * QP;             // 128 x VP  (V transposed: [n][k], k XOR 4*(n&7))
    float* Ps = Vt + HDIM * VP;           // BQ x PP

    const int tid  = threadIdx.x;
    const int warp = tid >> 5;
    const int lane = tid & 31;
    const int gid  = lane >> 2;
    const int tig  = lane & 3;
    const int b  = blockIdx.z;
    const int h  = blockIdx.y;
    const int g  = h >> 2;
    const int s0 = blockIdx.x * BQ;
    const int wr = warp * 16;

    // scale * log2(e): softmax done in base 2
    const float scale = 0.08838834764831845f * 1.4426950408889634f;

    // Load Q tile (scaled, tf32-rounded)
    const float* qg = q + ((size_t)(b * S_LEN + s0)) * DMODEL + h * HDIM;
    for (int i = tid; i < BQ * (HDIM / 4); i += 256) {
        int r = i >> 5, c4 = (i & 31) << 2;
        float4 t = *(const float4*)(qg + (size_t)r * DMODEL + c4);
        float* d = Qs + r * QP + c4;
        d[0] = f2tf(t.x * scale); d[1] = f2tf(t.y * scale);
        d[2] = f2tf(t.z * scale); d[3] = f2tf(t.w * scale);
    }

    float Oc[NTO][4];
#pragma unroll
    for (int i = 0; i < NTO; i++) { Oc[i][0] = Oc[i][1] = Oc[i][2] = Oc[i][3] = 0.f; }
    float m0r = -1e30f, m1r = -1e30f, l0 = 0.f, l1 = 0.f;

    const float* kg = k + (size_t)(b * S_LEN) * KVLD + g * HDIM;
    const float* vg = v + (size_t)(b * S_LEN) * KVLD + g * HDIM;

    // Staging registers
    float4 kst[8];
    float  vst[32];
    const int vc  = tid & 127;          // Vt column this thread fills
    const int vkh = tid >> 7;           // 0/1 -> k halves
    const unsigned vsw = 4u * (vc & 7); // k XOR swizzle for this column

    // Prefetch tile 0
    {
        const int kt0 = 0;
#pragma unroll
        for (int u = 0; u < 8; u++) {
            int i = tid + u * 256;
            int r = i >> 5, c4 = (i & 31) << 2;
            kst[u] = *(const float4*)(kg + (size_t)(kt0 + r) * KVLD + c4);
        }
#pragma unroll
        for (int it = 0; it < 32; it++) {
            int kk = vkh * 32 + it;
            vst[it] = vg[(size_t)(kt0 + kk) * KVLD + vc];
        }
    }

    for (int jt = 0; jt < NJT; jt++) {
        __syncthreads();   // previous tile's fragment reads complete
        // Store staged tile
#pragma unroll
        for (int u = 0; u < 8; u++) {
            int i = tid + u * 256;
            int r = i >> 5, c4 = (i & 31) << 2;
            float* d = Ks + r * QP + c4;
            d[0] = f2tf(kst[u].x); d[1] = f2tf(kst[u].y);
            d[2] = f2tf(kst[u].z); d[3] = f2tf(kst[u].w);
        }
#pragma unroll
        for (int it = 0; it < 32; it++) {
            int kk = vkh * 32 + it;
            Vt[vc * VP + (kk ^ vsw)] = f2tf(vst[it]);
        }
        __syncthreads();   // tile ready

        // Prefetch next tile into registers (overlaps with compute below)
        if (jt + 1 < NJT) {
            const int kt0 = (jt + 1) * BK;
#pragma unroll
            for (int u = 0; u < 8; u++) {
                int i = tid + u * 256;
                int r = i >> 5, c4 = (i & 31) << 2;
                kst[u] = *(const float4*)(kg + (size_t)(kt0 + r) * KVLD + c4);
            }
#pragma unroll
            for (int it = 0; it < 32; it++) {
                int kk = vkh * 32 + it;
                vst[it] = vg[(size_t)(kt0 + kk) * KVLD + vc];
            }
        }

        // ---- scores = Q @ K^T  (warp: 16 x 64), vectorized frags ----
        float sc[NTS][4];
#pragma unroll
        for (int i = 0; i < NTS; i++) { sc[i][0] = sc[i][1] = sc[i][2] = sc[i][3] = 0.f; }

#pragma unroll
        for (int ch = 0; ch < 4; ch++) {
            const int kc = ch * 32;
            float4 aq0 = *(const float4*)(Qs + (wr + gid)     * QP + kc + 4 * tig);
            float4 aq1 = *(const float4*)(Qs + (wr + gid + 8) * QP + kc + 4 * tig);
            float4 aq2 = *(const float4*)(Qs + (wr + gid)     * QP + kc + 16 + 4 * tig);
            float4 aq3 = *(const float4*)(Qs + (wr + gid + 8) * QP + kc + 16 + 4 * tig);
            const float* a0 = (const float*)&aq0;
            const float* a1 = (const float*)&aq1;
            const float* a2 = (const float*)&aq2;
            const float* a3 = (const float*)&aq3;
#pragma unroll
            for (int nt = 0; nt < NTS; nt++) {
                float4 bk0 = *(const float4*)(Ks + (nt * 8 + gid) * QP + kc + 4 * tig);
                float4 bk1 = *(const float4*)(Ks + (nt * 8 + gid) * QP + kc + 16 + 4 * tig);
                const float* b0 = (const float*)&bk0;
                const float* b1 = (const float*)&bk1;
#pragma unroll
                for (int s = 0; s < 4; s++)
                    mma_tf32(sc[nt], a0[s], a1[s], a2[s], a3[s], b0[s], b1[s]);
            }
        }

        // ---- online softmax (base 2), rows wr+gid and wr+gid+8 ----
        float mx0 = -1e30f, mx1 = -1e30f;
#pragma unroll
        for (int nt = 0; nt < NTS; nt++) {
            mx0 = fmaxf(mx0, fmaxf(sc[nt][0], sc[nt][1]));
            mx1 = fmaxf(mx1, fmaxf(sc[nt][2], sc[nt][3]));
        }
        mx0 = fmaxf(mx0, __shfl_xor_sync(0xffffffffu, mx0, 1));
        mx0 = fmaxf(mx0, __shfl_xor_sync(0xffffffffu, mx0, 2));
        mx1 = fmaxf(mx1, __shfl_xor_sync(0xffffffffu, mx1, 1));
        mx1 = fmaxf(mx1, __shfl_xor_sync(0xffffffffu, mx1, 2));
        const float mn0 = fmaxf(m0r, mx0), mn1 = fmaxf(m1r, mx1);
        const float al0 = ex2(m0r - mn0), al1 = ex2(m1r - mn1);
        m0r = mn0; m1r = mn1;

        float s0s = 0.f, s1s = 0.f;
#pragma unroll
        for (int nt = 0; nt < NTS; nt++) {
            float p0 = ex2(sc[nt][0] - mn0);
            float p1 = ex2(sc[nt][1] - mn0);
            float p2 = ex2(sc[nt][2] - mn1);
            float p3 = ex2(sc[nt][3] - mn1);
            s0s += p0 + p1; s1s += p2 + p3;
            Ps[(wr + gid)     * PP + nt * 8 + 2 * tig]     = f2tf(p0);
            Ps[(wr + gid)     * PP + nt * 8 + 2 * tig + 1] = f2tf(p1);
            Ps[(wr + gid + 8) * PP + nt * 8 + 2 * tig]     = f2tf(p2);
            Ps[(wr + gid + 8) * PP + nt * 8 + 2 * tig + 1] = f2tf(p3);
        }
        s0s += __shfl_xor_sync(0xffffffffu, s0s, 1);
        s0s += __shfl_xor_sync(0xffffffffu, s0s, 2);
        s1s += __shfl_xor_sync(0xffffffffu, s1s, 1);
        s1s += __shfl_xor_sync(0xffffffffu, s1s, 2);
        l0 = l0 * al0 + s0s;
        l1 = l1 * al1 + s1s;

#pragma unroll
        for (int nt = 0; nt < NTO; nt++) {
            Oc[nt][0] *= al0; Oc[nt][1] *= al0;
            Oc[nt][2] *= al1; Oc[nt][3] *= al1;
        }
        __syncwarp();   // Ps rows are warp-private

        // ---- O += P @ V   (warp: 16 x 128), Vt transposed + swizzled ----
#pragma unroll
        for (int ch = 0; ch < 2; ch++) {
            const int kc = ch * 32;
            float4 ap0 = *(const float4*)(Ps + (wr + gid)     * PP + kc + 4 * tig);
            float4 ap1 = *(const float4*)(Ps + (wr + gid + 8) * PP + kc + 4 * tig);
            float4 ap2 = *(const float4*)(Ps + (wr + gid)     * PP + kc + 16 + 4 * tig);
            float4 ap3 = *(const float4*)(Ps + (wr + gid + 8) * PP + kc + 16 + 4 * tig);
            const float* a0 = (const float*)&ap0;
            const float* a1 = (const float*)&ap1;
            const float* a2 = (const float*)&ap2;
            const float* a3 = (const float*)&ap3;
#pragma unroll
            for (int nt = 0; nt < NTO; nt++) {
                const int n = nt * 8 + gid;
                const unsigned sw = 4u * (unsigned)gid;
                float4 bv0 = *(const float4*)(Vt + n * VP + ((unsigned)(kc + 4 * tig) ^ sw));
                float4 bv1 = *(const float4*)(Vt + n * VP + ((unsigned)(kc + 16 + 4 * tig) ^ sw));
                const float* b0 = (const float*)&bv0;
                const float* b1 = (const float*)&bv1;
#pragma unroll
                for (int s = 0; s < 4; s++)
                    mma_tf32(Oc[nt], a0[s], a1[s], a2[s], a3[s], b0[s], b1[s]);
            }
        }
    }

    // Epilogue: normalize, round to tf32 (so proj needs no conversion), store
    const float il0 = 1.f / l0, il1 = 1.f / l1;
    float* og = g_attn + (size_t)(b * S_LEN + s0) * DMODEL + h * HDIM;
#pragma unroll
    for (int nt = 0; nt < NTO; nt++) {
        const int col = nt * 8 + 2 * tig;
        og[(size_t)(wr + gid)     * DMODEL + col]     = f2tf(Oc[nt][0] * il0);
        og[(size_t)(wr + gid)     * DMODEL + col + 1] = f2tf(Oc[nt][1] * il0);
        og[(size_t)(wr + gid + 8) * DMODEL + col]     = f2tf(Oc[nt][2] * il1);
        og[(size_t)(wr + gid + 8) * DMODEL + col + 1] = f2tf(Oc[nt][3] * il1);
    }
}

// ---------------------------------------------------------------------------
// Projection: out[m][n] = sum_k g_attn[m][k] * Wc[n][k] + bc[n]
// Tile 256(M) x 128(N), K chunk 32. 8 warps, warp owns 32 rows (B amortized 2x).
// Register-staged prefetch hides gmem latency. g_attn is pre-tf32-rounded.
// ---------------------------------------------------------------------------
__global__ __launch_bounds__(256, 1)
void proj_kernel(const float* __restrict__ Wc,
                 const float* __restrict__ bc,
                 float* __restrict__ out)
{
    extern __shared__ float psm[];
    float* As = psm;                 // PTM x GP
    float* Bs = As + PTM * GP;       // PTN x GP

    const int tid  = threadIdx.x;
    const int warp = tid >> 5;
    const int lane = tid & 31;
    const int gid  = lane >> 2;
    const int tig  = lane & 3;
    const int n0 = blockIdx.x * PTN;
    const int m0 = blockIdx.y * PTM;
    const int wr = warp * 32;

    float acc[2][16][4];
#pragma unroll
    for (int p = 0; p < 2; p++)
#pragma unroll
        for (int i = 0; i < 16; i++) {
            acc[p][i][0] = acc[p][i][1] = acc[p][i][2] = acc[p][i][3] = 0.f;
        }

    float4 ast[8], bst[4];
    // Prefetch chunk 0
#pragma unroll
    for (int u = 0; u < 8; u++) {
        int i = tid + u * 256;
        int r = i >> 3, c4 = (i & 7) << 2;
        ast[u] = *(const float4*)(g_attn + (size_t)(m0 + r) * DMODEL + c4);
    }
#pragma unroll
    for (int u = 0; u < 4; u++) {
        int i = tid + u * 256;
        int r = i >> 3, c4 = (i & 7) << 2;
        bst[u] = *(const float4*)(Wc + (size_t)(n0 + r) * DMODEL + c4);
    }

    for (int j = 0; j < DMODEL / PTK; j++) {
        __syncthreads();
#pragma unroll
        for (int u = 0; u < 8; u++) {
            int i = tid + u * 256;
            int r = i >> 3, c4 = (i & 7) << 2;
            *(float4*)(As + r * GP + c4) = ast[u];   // already tf32-rounded
        }
#pragma unroll
        for (int u = 0; u < 4; u++) {
            int i = tid + u * 256;
            int r = i >> 3, c4 = (i & 7) << 2;
            float* d = Bs + r * GP + c4;
            d[0] = f2tf(bst[u].x); d[1] = f2tf(bst[u].y);
            d[2] = f2tf(bst[u].z); d[3] = f2tf(bst[u].w);
        }
        __syncthreads();

        if (j + 1 < DMODEL / PTK) {
            const int kc = (j + 1) * PTK;
#pragma unroll
            for (int u = 0; u < 8; u++) {
                int i = tid + u * 256;
                int r = i >> 3, c4 = (i & 7) << 2;
                ast[u] = *(const float4*)(g_attn + (size_t)(m0 + r) * DMODEL + kc + c4);
            }
#pragma unroll
            for (int u = 0; u < 4; u++) {
                int i = tid + u * 256;
                int r = i >> 3, c4 = (i & 7) << 2;
                bst[u] = *(const float4*)(Wc + (size_t)(n0 + r) * DMODEL + kc + c4);
            }
        }

        // A frags: two 16-row pairs
        float4 a00 = *(const float4*)(As + (wr + gid)      * GP + 4 * tig);
        float4 a01 = *(const float4*)(As + (wr + gid + 8)  * GP + 4 * tig);
        float4 a02 = *(const float4*)(As + (wr + gid)      * GP + 16 + 4 * tig);
        float4 a03 = *(const float4*)(As + (wr + gid + 8)  * GP + 16 + 4 * tig);
        float4 a10 = *(const float4*)(As + (wr + gid + 16) * GP + 4 * tig);
        float4 a11 = *(const float4*)(As + (wr + gid + 24) * GP + 4 * tig);
        float4 a12 = *(const float4*)(As + (wr + gid + 16) * GP + 16 + 4 * tig);
        float4 a13 = *(const float4*)(As + (wr + gid + 24) * GP + 16 + 4 * tig);
        const float* p00 = (const float*)&a00; const float* p01 = (const float*)&a01;
        const float* p02 = (const float*)&a02; const float* p03 = (const float*)&a03;
        const float* p10 = (const float*)&a10; const float* p11 = (const float*)&a11;
        const float* p12 = (const float*)&a12; const float* p13 = (const float*)&a13;

#pragma unroll
        for (int nt = 0; nt < 16; nt++) {
            float4 bb0 = *(const float4*)(Bs + (nt * 8 + gid) * GP + 4 * tig);
            float4 bb1 = *(const float4*)(Bs + (nt * 8 + gid) * GP + 16 + 4 * tig);
            const float* b0 = (const float*)&bb0;
            const float* b1 = (const float*)&bb1;
#pragma unroll
            for (int s = 0; s < 4; s++) {
                mma_tf32(acc[0][nt], p00[s], p01[s], p02[s], p03[s], b0[s], b1[s]);
                mma_tf32(acc[1][nt], p10[s], p11[s], p12[s], p13[s], b0[s], b1[s]);
            }
        }
    }

    // Epilogue: bias + store
#pragma unroll
    for (int p = 0; p < 2; p++) {
        const int r0 = m0 + wr + p * 16 + gid;
#pragma unroll
        for (int nt = 0; nt < 16; nt++) {
            const int col = n0 + nt * 8 + 2 * tig;
            const float b0v = bc[col], b1v = bc[col + 1];
            float2 o0 = { acc[p][nt][0] + b0v, acc[p][nt][1] + b1v };
            float2 o1 = { acc[p][nt][2] + b0v, acc[p][nt][3] + b1v };
            *(float2*)(out + (size_t)r0       * DMODEL + col) = o0;
            *(float2*)(out + (size_t)(r0 + 8) * DMODEL + col) = o1;
        }
    }
}

// ---------------------------------------------------------------------------
extern "C" void kernel_launch(void* const* d_in, const int* in_sizes, int n_in,
                              void* d_out, int out_size)
{
    const float* q  = (const float*)d_in[0];
    const float* k  = (const float*)d_in[1];
    const float* v  = (const float*)d_in[2];
    const float* Wc = (const float*)d_in[3];
    const float* bc = (const float*)d_in[4];
    float* out = (float*)d_out;

    const int attn_smem = (BQ * QP + BK * QP + HDIM * VP + BQ * PP) * (int)sizeof(float);
    const int proj_smem = (PTM * GP + PTN * GP) * (int)sizeof(float);
    cudaFuncSetAttribute(attn_kernel, cudaFuncAttributeMaxDynamicSharedMemorySize, attn_smem);
    cudaFuncSetAttribute(proj_kernel, cudaFuncAttributeMaxDynamicSharedMemorySize, proj_smem);

    dim3 agrid(S_LEN / BQ, NH, BATCH);
    attn_kernel<<<agrid, 256, attn_smem>>>(q, k, v);

    dim3 pgrid(DMODEL / PTN, (BATCH * S_LEN) / PTM);
    proj_kernel<<<pgrid, 256, proj_smem>>>(Wc, bc, out);
}

// round 4
// speedup vs baseline: 2.4614x; 2.4614x over previous
#include <cuda_runtime.h>
#include <cuda_fp16.h>
#include <math.h>
#include <stdint.h>

// Problem constants
#define S_LEN  2048
#define DMODEL 2048
#define HDIM   128
#define NH     16
#define NG     4
#define BATCH  2
#define KVLD   (NG * HDIM)   // 512

// Attention tiling
#define BQ    128
#define BK    64
#define NJT   (S_LEN / BK)   // 32
#define QPH   160            // Q/K smem pitch in halves (320B = 80 words ≡ 16 mod 32)
#define VPH   96             // Vt pitch in halves (192B = 48 words ≡ 16 mod 32)
#define PPH   96             // P  pitch in halves
// smem offsets (halves)
#define OFF_QS   0
#define OFF_KS0  (BQ * QPH)                 // 20480
#define OFF_KS1  (OFF_KS0 + BK * QPH)       // 30720
#define OFF_VT0  (OFF_KS1 + BK * QPH)       // 40960
#define OFF_VT1  (OFF_VT0 + HDIM * VPH)     // 53248
#define OFF_PS   (OFF_VT1 + HDIM * VPH)     // 65536
#define ATTN_SMEM_HALVES (OFF_PS + BQ * PPH)
#define ATTN_SMEM_BYTES  (ATTN_SMEM_HALVES * 2)

// Projection tiling: 256(M) x 128(N), K-chunk 64 halves (two 32-half subs)
#define PTM   256
#define PTN   128
#define PTKC  64
#define POFF_A0  0
#define POFF_A1  (PTM * PTKC)               // 16384
#define POFF_B0  (2 * PTM * PTKC)           // 32768
#define POFF_B1  (2 * PTM * PTKC + PTN * PTKC)
#define PROJ_SMEM_HALVES (2 * PTM * PTKC + 2 * PTN * PTKC)
#define PROJ_SMEM_BYTES  (PROJ_SMEM_HALVES * 2)

// fp16 globals
__device__ __half g_kh[(size_t)BATCH * S_LEN * KVLD];             // [b][s][g*128+d]
__device__ __half g_vt[(size_t)BATCH * NG * HDIM * S_LEN];        // [b][g][d][s]
__device__ __half g_wh[(size_t)DMODEL * DMODEL];                  // [n][k]
__device__ __half g_attn[(size_t)BATCH * S_LEN * DMODEL];         // [m][k]

__device__ __forceinline__ float ex2(float x) {
    float r; asm("ex2.approx.f32 %0, %1;" : "=f"(r) : "f"(x)); return r;
}

__device__ __forceinline__ void mma_f16(float c[4],
    uint32_t a0, uint32_t a1, uint32_t a2, uint32_t a3, uint32_t b0, uint32_t b1)
{
    asm volatile(
        "mma.sync.aligned.m16n8k16.row.col.f32.f16.f16.f32 "
        "{%0,%1,%2,%3}, {%4,%5,%6,%7}, {%8,%9}, {%0,%1,%2,%3};"
        : "+f"(c[0]), "+f"(c[1]), "+f"(c[2]), "+f"(c[3])
        : "r"(a0), "r"(a1), "r"(a2), "r"(a3), "r"(b0), "r"(b1));
}

#define CP16(dst, src) asm volatile( \
    "cp.async.cg.shared.global [%0], [%1], 16;" :: "r"(dst), "l"(src))
#define CPCOMMIT() asm volatile("cp.async.commit_group;")
#define CPWAIT1()  asm volatile("cp.async.wait_group 1;")

// ---------------------------------------------------------------------------
// Pre-pass: f32 -> f16 flat convert (n % 4 == 0)
// ---------------------------------------------------------------------------
__global__ void conv_kernel(const float* __restrict__ src, __half* __restrict__ dst, int n)
{
    int i = (blockIdx.x * blockDim.x + threadIdx.x) * 4;
    if (i < n) {
        float4 t = *(const float4*)(src + i);
        *(__half2*)(dst + i)     = __floats2half2_rn(t.x, t.y);
        *(__half2*)(dst + i + 2) = __floats2half2_rn(t.z, t.w);
    }
}

// Pre-pass: V transpose  v[b][s][g*128+d] -> g_vt[b][g][d][s], fp16
__global__ void vtrans_kernel(const float* __restrict__ v)
{
    __shared__ float t[32][33];
    const int b = blockIdx.z >> 2, g = blockIdx.z & 3;
    const int d0 = blockIdx.y * 32, s0 = blockIdx.x * 32;
    const int tx = threadIdx.x, ty = threadIdx.y;
#pragma unroll
    for (int i = 0; i < 32; i += 8)
        t[ty + i][tx] = v[(size_t)(b * S_LEN + s0 + ty + i) * KVLD + g * HDIM + d0 + tx];
    __syncthreads();
#pragma unroll
    for (int i = 0; i < 32; i += 8)
        g_vt[((size_t)(b * NG + g) * HDIM + d0 + ty + i) * S_LEN + s0 + tx] =
            __float2half_rn(t[tx][ty + i]);
}

// ---------------------------------------------------------------------------
// Flash attention, fp16 m16n8k16, online softmax (base-2), cp.async pipeline.
// Grid: (S/BQ, NH, B). Block 256 = 8 warps; warp owns 16 Q rows.
// k-permutation: per 32-k block, thread tig covers k = 8*tig..8*tig+7; halves
// 0-3 of the uint4 feed mma "chunk0" (kgroups {8t,8t+1},{8t+2,8t+3}), halves
// 4-7 feed chunk1. A and B use the same mapping -> correct contraction.
// ---------------------------------------------------------------------------
__global__ __launch_bounds__(256, 1)
void attn_kernel(const float* __restrict__ q)
{
    extern __shared__ __half sh[];
    const uint32_t sbase = (uint32_t)__cvta_generic_to_shared(sh);

    const int tid  = threadIdx.x;
    const int warp = tid >> 5;
    const int lane = tid & 31;
    const int gid  = lane >> 2;
    const int tig  = lane & 3;
    const int b  = blockIdx.z;
    const int h  = blockIdx.y;
    const int g  = h >> 2;
    const int s0 = blockIdx.x * BQ;
    const int wr = warp * 16;

    // scale * log2(e), folded into Q (softmax in base 2)
    const float scale = 0.08838834764831845f * 1.4426950408889634f;

    // Load + convert Q tile once (f32 -> f16, scaled)
    const float* qg = q + ((size_t)(b * S_LEN + s0)) * DMODEL + h * HDIM;
    for (int i = tid; i < BQ * (HDIM / 4); i += 256) {
        int r = i >> 5, c4 = (i & 31) << 2;
        float4 t = *(const float4*)(qg + (size_t)r * DMODEL + c4);
        __half* d = sh + OFF_QS + r * QPH + c4;
        *(__half2*)(d)     = __floats2half2_rn(t.x * scale, t.y * scale);
        *(__half2*)(d + 2) = __floats2half2_rn(t.z * scale, t.w * scale);
    }

    // cp.async source bases
    const __half* khb = g_kh + (size_t)b * S_LEN * KVLD + g * HDIM;
    const __half* vtb = g_vt + (size_t)(b * NG + g) * HDIM * S_LEN;

    // loader thread coordinates
    const int kr = tid >> 4, kc = (tid & 15);      // per-u stride handled below
    (void)kr; (void)kc;

    // issue one tile's cp.asyncs into buffer p
    auto issue_tile = [&](int jt, int p) {
        const int kt0 = jt * BK;
        const uint32_t ksOff = sbase + (p ? OFF_KS1 : OFF_KS0) * 2;
        const uint32_t vtOff = sbase + (p ? OFF_VT1 : OFF_VT0) * 2;
#pragma unroll
        for (int u = 0; u < 4; u++) {
            int idx = tid + u * 256;
            int r = idx >> 4, c = idx & 15;                    // K: 64 rows x 16 chunks
            CP16(ksOff + (uint32_t)(r * QPH + c * 8) * 2,
                 khb + (size_t)(kt0 + r) * KVLD + c * 8);
        }
#pragma unroll
        for (int u = 0; u < 4; u++) {
            int idx = tid + u * 256;
            int d = idx >> 3, c = idx & 7;                     // V: 128 rows x 8 chunks
            CP16(vtOff + (uint32_t)(d * VPH + c * 8) * 2,
                 vtb + (size_t)d * S_LEN + kt0 + c * 8);
        }
    };

    issue_tile(0, 0);
    CPCOMMIT();

    float Oc[16][4];
#pragma unroll
    for (int i = 0; i < 16; i++) { Oc[i][0] = Oc[i][1] = Oc[i][2] = Oc[i][3] = 0.f; }
    float m0r = -1e30f, m1r = -1e30f, l0 = 0.f, l1 = 0.f;

    for (int jt = 0; jt < NJT; jt++) {
        const int p = jt & 1;
        if (jt + 1 < NJT) issue_tile(jt + 1, p ^ 1);
        CPCOMMIT();
        CPWAIT1();
        __syncthreads();   // tile jt ready for all warps

        const __half* Ks = sh + (p ? OFF_KS1 : OFF_KS0);
        const __half* Vt = sh + (p ? OFF_VT1 : OFF_VT0);
        __half* Ps = sh + OFF_PS;

        // ---- scores = Q @ K^T  (warp: 16 x 64) ----
        float sc[8][4];
#pragma unroll
        for (int i = 0; i < 8; i++) { sc[i][0] = sc[i][1] = sc[i][2] = sc[i][3] = 0.f; }

#pragma unroll
        for (int bi = 0; bi < 4; bi++) {
            const int kk = bi * 32 + 8 * tig;
            uint4 A0 = *(const uint4*)(sh + OFF_QS + (wr + gid)     * QPH + kk);
            uint4 A1 = *(const uint4*)(sh + OFF_QS + (wr + gid + 8) * QPH + kk);
#pragma unroll
            for (int nt = 0; nt < 8; nt++) {
                uint4 B = *(const uint4*)(Ks + (nt * 8 + gid) * QPH + kk);
                mma_f16(sc[nt], A0.x, A1.x, A0.y, A1.y, B.x, B.y);
                mma_f16(sc[nt], A0.z, A1.z, A0.w, A1.w, B.z, B.w);
            }
        }

        // ---- online softmax (base 2) ----
        float mx0 = -1e30f, mx1 = -1e30f;
#pragma unroll
        for (int nt = 0; nt < 8; nt++) {
            mx0 = fmaxf(mx0, fmaxf(sc[nt][0], sc[nt][1]));
            mx1 = fmaxf(mx1, fmaxf(sc[nt][2], sc[nt][3]));
        }
        mx0 = fmaxf(mx0, __shfl_xor_sync(0xffffffffu, mx0, 1));
        mx0 = fmaxf(mx0, __shfl_xor_sync(0xffffffffu, mx0, 2));
        mx1 = fmaxf(mx1, __shfl_xor_sync(0xffffffffu, mx1, 1));
        mx1 = fmaxf(mx1, __shfl_xor_sync(0xffffffffu, mx1, 2));
        const float mn0 = fmaxf(m0r, mx0), mn1 = fmaxf(m1r, mx1);
        const float al0 = ex2(m0r - mn0), al1 = ex2(m1r - mn1);
        m0r = mn0; m1r = mn1;

        float s0s = 0.f, s1s = 0.f;
#pragma unroll
        for (int nt = 0; nt < 8; nt++) {
            float p0 = ex2(sc[nt][0] - mn0);
            float p1 = ex2(sc[nt][1] - mn0);
            float p2 = ex2(sc[nt][2] - mn1);
            float p3 = ex2(sc[nt][3] - mn1);
            s0s += p0 + p1; s1s += p2 + p3;
            *(__half2*)(Ps + (wr + gid)     * PPH + nt * 8 + 2 * tig) = __floats2half2_rn(p0, p1);
            *(__half2*)(Ps + (wr + gid + 8) * PPH + nt * 8 + 2 * tig) = __floats2half2_rn(p2, p3);
        }
        s0s += __shfl_xor_sync(0xffffffffu, s0s, 1);
        s0s += __shfl_xor_sync(0xffffffffu, s0s, 2);
        s1s += __shfl_xor_sync(0xffffffffu, s1s, 1);
        s1s += __shfl_xor_sync(0xffffffffu, s1s, 2);
        l0 = l0 * al0 + s0s;
        l1 = l1 * al1 + s1s;

#pragma unroll
        for (int nt = 0; nt < 16; nt++) {
            Oc[nt][0] *= al0; Oc[nt][1] *= al0;
            Oc[nt][2] *= al1; Oc[nt][3] *= al1;
        }
        __syncwarp();   // Ps rows are warp-private

        // ---- O += P @ V  (warp: 16 x 128) ----
#pragma unroll
        for (int bi = 0; bi < 2; bi++) {
            const int kk = bi * 32 + 8 * tig;
            uint4 A0 = *(const uint4*)(Ps + (wr + gid)     * PPH + kk);
            uint4 A1 = *(const uint4*)(Ps + (wr + gid + 8) * PPH + kk);
#pragma unroll
            for (int nt = 0; nt < 16; nt++) {
                uint4 B = *(const uint4*)(Vt + (nt * 8 + gid) * VPH + kk);
                mma_f16(Oc[nt], A0.x, A1.x, A0.y, A1.y, B.x, B.y);
                mma_f16(Oc[nt], A0.z, A1.z, A0.w, A1.w, B.z, B.w);
            }
        }
        __syncthreads();   // all warps done with buffer p before it is refilled
    }

    // Epilogue: normalize, convert to fp16, store to g_attn
    const float il0 = 1.f / l0, il1 = 1.f / l1;
    __half* og = g_attn + (size_t)(b * S_LEN + s0) * DMODEL + h * HDIM;
#pragma unroll
    for (int nt = 0; nt < 16; nt++) {
        const int col = nt * 8 + 2 * tig;
        *(__half2*)(og + (size_t)(wr + gid)     * DMODEL + col) =
            __floats2half2_rn(Oc[nt][0] * il0, Oc[nt][1] * il0);
        *(__half2*)(og + (size_t)(wr + gid + 8) * DMODEL + col) =
            __floats2half2_rn(Oc[nt][2] * il1, Oc[nt][3] * il1);
    }
}

// ---------------------------------------------------------------------------
// Projection: out[m][n] = sum_k g_attn[m][k] * Wh[n][k] + bc[n]  (fp16 mma)
// Tile 256(M) x 128(N), K-chunk 64 halves. 8 warps, warp owns 32 rows.
// A/B smem as [sub(32k)][row][32 halves] contiguous -> conflict-free LDS.128.
// ---------------------------------------------------------------------------
__global__ __launch_bounds__(256, 1)
void proj_kernel(const float* __restrict__ bc, float* __restrict__ out)
{
    extern __shared__ __half sh[];
    const uint32_t sbase = (uint32_t)__cvta_generic_to_shared(sh);

    const int tid  = threadIdx.x;
    const int warp = tid >> 5;
    const int lane = tid & 31;
    const int gid  = lane >> 2;
    const int tig  = lane & 3;
    const int n0 = blockIdx.x * PTN;
    const int m0 = blockIdx.y * PTM;
    const int wr = warp * 32;

    const __half* Ag = g_attn + (size_t)m0 * DMODEL;
    const __half* Bg = g_wh   + (size_t)n0 * DMODEL;

    auto issue_tile = [&](int j, int p) {
        const int kc = j * PTKC;
        const uint32_t aOff = sbase + (p ? POFF_A1 : POFF_A0) * 2;
        const uint32_t bOff = sbase + (p ? POFF_B1 : POFF_B0) * 2;
#pragma unroll
        for (int u = 0; u < 8; u++) {                      // A: 256 rows x 8 chunks
            int idx = tid + u * 256;
            int r = idx >> 3, c = idx & 7;
            int sub = c >> 2;
            CP16(aOff + (uint32_t)(sub * (PTM * 32) + r * 32 + (c & 3) * 8) * 2,
                 Ag + (size_t)r * DMODEL + kc + c * 8);
        }
#pragma unroll
        for (int u = 0; u < 4; u++) {                      // B: 128 rows x 8 chunks
            int idx = tid + u * 256;
            int r = idx >> 3, c = idx & 7;
            int sub = c >> 2;
            CP16(bOff + (uint32_t)(sub * (PTN * 32) + r * 32 + (c & 3) * 8) * 2,
                 Bg + (size_t)r * DMODEL + kc + c * 8);
        }
    };

    float acc[2][16][4];
#pragma unroll
    for (int p = 0; p < 2; p++)
#pragma unroll
        for (int i = 0; i < 16; i++) {
            acc[p][i][0] = acc[p][i][1] = acc[p][i][2] = acc[p][i][3] = 0.f;
        }

    issue_tile(0, 0);
    CPCOMMIT();

    const int NCH = DMODEL / PTKC;   // 32
    for (int j = 0; j < NCH; j++) {
        const int p = j & 1;
        if (j + 1 < NCH) issue_tile(j + 1, p ^ 1);
        CPCOMMIT();
        CPWAIT1();
        __syncthreads();

        const __half* As = sh + (p ? POFF_A1 : POFF_A0);
        const __half* Bs = sh + (p ? POFF_B1 : POFF_B0);

#pragma unroll
        for (int sub = 0; sub < 2; sub++) {
            const __half* Asub = As + sub * (PTM * 32);
            const __half* Bsub = Bs + sub * (PTN * 32);
            const int kk = 8 * tig;
            uint4 A0 = *(const uint4*)(Asub + (wr + gid)      * 32 + kk);
            uint4 A1 = *(const uint4*)(Asub + (wr + gid + 8)  * 32 + kk);
            uint4 A2 = *(const uint4*)(Asub + (wr + gid + 16) * 32 + kk);
            uint4 A3 = *(const uint4*)(Asub + (wr + gid + 24) * 32 + kk);
#pragma unroll
            for (int nt = 0; nt < 16; nt++) {
                uint4 B = *(const uint4*)(Bsub + (nt * 8 + gid) * 32 + kk);
                mma_f16(acc[0][nt], A0.x, A1.x, A0.y, A1.y, B.x, B.y);
                mma_f16(acc[0][nt], A0.z, A1.z, A0.w, A1.w, B.z, B.w);
                mma_f16(acc[1][nt], A2.x, A3.x, A2.y, A3.y, B.x, B.y);
                mma_f16(acc[1][nt], A2.z, A3.z, A2.w, A3.w, B.z, B.w);
            }
        }
        __syncthreads();
    }

    // Epilogue: bias + store
#pragma unroll
    for (int p = 0; p < 2; p++) {
        const int r0 = m0 + wr + p * 16 + gid;
#pragma unroll
        for (int nt = 0; nt < 16; nt++) {
            const int col = n0 + nt * 8 + 2 * tig;
            const float b0v = bc[col], b1v = bc[col + 1];
            float2 o0 = { acc[p][nt][0] + b0v, acc[p][nt][1] + b1v };
            float2 o1 = { acc[p][nt][2] + b0v, acc[p][nt][3] + b1v };
            *(float2*)(out + (size_t)r0       * DMODEL + col) = o0;
            *(float2*)(out + (size_t)(r0 + 8) * DMODEL + col) = o1;
        }
    }
}

// ---------------------------------------------------------------------------
extern "C" void kernel_launch(void* const* d_in, const int* in_sizes, int n_in,
                              void* d_out, int out_size)
{
    const float* q  = (const float*)d_in[0];
    const float* k  = (const float*)d_in[1];
    const float* v  = (const float*)d_in[2];
    const float* Wc = (const float*)d_in[3];
    const float* bc = (const float*)d_in[4];
    float* out = (float*)d_out;

    __half* kh_p; cudaGetSymbolAddress((void**)&kh_p, g_kh);
    __half* wh_p; cudaGetSymbolAddress((void**)&wh_p, g_wh);

    // Pre-passes: f32 -> f16 (K, Wc) and V transpose
    {
        int nk = BATCH * S_LEN * KVLD;       // 2,097,152
        conv_kernel<<<nk / 4 / 256, 256>>>(k, kh_p, nk);
        int nw = DMODEL * DMODEL;            // 4,194,304
        conv_kernel<<<nw / 4 / 256, 256>>>(Wc, wh_p, nw);
        dim3 tg(S_LEN / 32, HDIM / 32, BATCH * NG);
        vtrans_kernel<<<tg, dim3(32, 8)>>>(v);
    }

    cudaFuncSetAttribute(attn_kernel, cudaFuncAttributeMaxDynamicSharedMemorySize, ATTN_SMEM_BYTES);
    cudaFuncSetAttribute(proj_kernel, cudaFuncAttributeMaxDynamicSharedMemorySize, PROJ_SMEM_BYTES);

    dim3 agrid(S_LEN / BQ, NH, BATCH);
    attn_kernel<<<agrid, 256, ATTN_SMEM_BYTES>>>(q);

    dim3 pgrid(DMODEL / PTN, (BATCH * S_LEN) / PTM);
    proj_kernel<<<pgrid, 256, PROJ_SMEM_BYTES>>>(bc, out);
}